// round 10
// baseline (speedup 1.0000x reference)
#include <cuda_runtime.h>

// SparsifyAttention: attn [64,8,192,192] fp32.
// out[j] = exp(v_j - t1) * sum_i [v_j >= t_i] * w_i / Z_i,
//   Z_i = sum_{v>=t_i} exp(v - t1)   (shift-invariant softmax).
// t_i = {96,128,144,153}-th largest per row.
//
// TWO rows per warp: 16 lanes per row, 12 values per lane. All warp-wide
// shared work (suffix scan, per-k bin locate, ballot/shfl/REDUX) is issued
// once and serves both rows via disjoint 16-lane member masks.
// 256-bin histogram over [-1.6, 0.8]; exact in-bin multiset select keeps
// correctness for ANY input (bins only narrow candidates).

#define FULLMASK 0xffffffffu

constexpr int   C     = 192;
constexpr int   VPT   = 12;      // values per lane (192 / 16)
constexpr int   RPB   = 16;      // rows per block (8 warps * 2)
constexpr int   NBINS = 256;
constexpr float BLO   = -1.6f;
constexpr float BHI   = 0.8f;
constexpr float BINV  = 1.0f / (BHI - BLO);
constexpr float FPSCALE  = 16384.0f;        // 2^14
constexpr float IFPSCALE = 1.0f / 16384.0f;

__device__ __forceinline__ unsigned f2ord(float f) {
    unsigned u = __float_as_uint(f);
    unsigned m = (unsigned)(((int)u) >> 31) | 0x80000000u;
    return u ^ m;
}
__device__ __forceinline__ float ord2f(unsigned x) {
    unsigned m = (~(unsigned)(((int)x) >> 31)) | 0x80000000u;
    return __uint_as_float(x ^ m);
}

// K-th largest (1-based, multiset) of this 16-lane group's 192 values.
// s0: lane's 16-bin chunk total. p0..p3: byte-packed chunk suffix sums
// S[0..15] (S[i] = count in bins [16*sub+i, 16*sub+16), all <= 192).
// suf: inclusive suffix of s0 over lanes sub..15 within the group.
template <int K>
__device__ __forceinline__ float sel_kth(
    int s0, unsigned p0, unsigned p1, unsigned p2, unsigned p3, int suf,
    const float v[VPT], const int bin[VPT],
    unsigned gmask, int gsh)
{
    const int above = suf - s0;
    const int r0 = K - above;              // meaningful on owning lane only
    const int r0c = max(1, min(255, r0));
    const unsigned sp = (unsigned)r0c * 0x01010101u;
    // i = (# of S[j] >= r0) - 1 : threshold bin index within the chunk.
    const int cnt = __popc(__vcmpgeu4(p0, sp)) + __popc(__vcmpgeu4(p1, sp))
                  + __popc(__vcmpgeu4(p2, sp)) + __popc(__vcmpgeu4(p3, sp));
    const int i = (cnt >> 3) - 1;
    const int idx = i + 1;                 // S[i+1], with S[16] = 0
    const unsigned pw = (idx >= 8) ? ((idx >= 12) ? p3 : p2)
                                   : ((idx >= 4) ? p1 : p0);
    const int sip1 = (idx >= 16) ? 0 : (int)(__byte_perm(pw, 0, idx & 3) & 0xFFu);
    const int r_loc = r0 - sip1;           // rank within bin, from top

    const unsigned ball = __ballot_sync(FULLMASK, (suf >= K) && (above < K));
    const int Lsub = __ffs((ball >> gsh) & 0xFFFFu) - 1;
    const int src = gsh + Lsub;            // absolute owning lane
    const int b = (Lsub << 4) + __shfl_sync(FULLMASK, i, src);
    const int r = __shfl_sync(FULLMASK, r_loc, src);

    // Fast path: bin max (exact when r == 1, the common case by bin design).
    float loc = -__int_as_float(0x7f800000);
    #pragma unroll
    for (int j = 0; j < VPT; j++)
        if (bin[j] == b) loc = fmaxf(loc, v[j]);
    unsigned mx = __reduce_max_sync(gmask, f2ord(loc));

    if (r > 1) {  // group-uniform, rare: exact multiset select within bin b
        int need = r;
        float bound = __int_as_float(0x7f800000);
        while (true) {
            loc = -__int_as_float(0x7f800000);
            #pragma unroll
            for (int j = 0; j < VPT; j++)
                if (bin[j] == b && v[j] < bound) loc = fmaxf(loc, v[j]);
            mx = __reduce_max_sync(gmask, f2ord(loc));
            const float fmx = ord2f(mx);
            int eq = 0;
            #pragma unroll
            for (int j = 0; j < VPT; j++)
                eq += (bin[j] == b) & (v[j] == fmx);
            need -= (int)__reduce_add_sync(gmask, (unsigned)eq);
            if (need <= 0) break;
            bound = fmx;
        }
    }
    return ord2f(mx);
}

__global__ __launch_bounds__(256, 5)
void sparsify_attention_kernel(
    const float* __restrict__ attn,
    const float* __restrict__ w1p, const float* __restrict__ w2p,
    const float* __restrict__ w3p, const float* __restrict__ w4p,
    float* __restrict__ out, int nrows)
{
    __shared__ unsigned hist_s[RPB][NBINS];

    const int lane = threadIdx.x & 31;
    const int wid  = threadIdx.x >> 5;
    const int grp  = lane >> 4;            // 0 or 1: which row of the pair
    const int sub  = lane & 15;            // lane within the 16-lane group
    const int gsh  = grp << 4;
    const unsigned gmask = 0xFFFFu << gsh;

    const int lrow = wid * 2 + grp;
    const long long row = (long long)blockIdx.x * RPB + lrow;
    if (row >= nrows) return;              // nrows % 16 == 0: warp-coherent

    unsigned* hist = hist_s[lrow];

    // Zero this row's histogram: 16 u32 per lane (4 x 128-bit stores).
    const uint4 zz = make_uint4(0, 0, 0, 0);
    #pragma unroll
    for (int q = 0; q < 4; q++)
        *reinterpret_cast<uint4*>(&hist[sub * 16 + q * 4]) = zz;
    __syncwarp();

    // Vectorized row load: 6 float2 per lane.
    const float2* rp2 = reinterpret_cast<const float2*>(attn + row * (long long)C);
    float v[VPT];
    #pragma unroll
    for (int jj = 0; jj < 6; jj++) {
        float2 f = rp2[sub + 16 * jj];
        v[2 * jj]     = f.x;
        v[2 * jj + 1] = f.y;
    }

    // Bin + histogram.
    int bin[VPT];
    #pragma unroll
    for (int j = 0; j < VPT; j++) {
        const float f = __saturatef((v[j] - BLO) * BINV);
        const int bi = (int)(f * 255.0f);
        bin[j] = bi;
        atomicAdd(&hist[bi], 1u);
    }
    __syncwarp();

    // Chunk counts (16 bins) -> byte-packed suffix sums.
    const uint4 c0 = *reinterpret_cast<const uint4*>(&hist[sub * 16]);
    const uint4 c1 = *reinterpret_cast<const uint4*>(&hist[sub * 16 + 4]);
    const uint4 c2 = *reinterpret_cast<const uint4*>(&hist[sub * 16 + 8]);
    const uint4 c3 = *reinterpret_cast<const uint4*>(&hist[sub * 16 + 12]);
    const int s15 = (int)c3.w;
    const int s14 = s15 + (int)c3.z;
    const int s13 = s14 + (int)c3.y;
    const int s12 = s13 + (int)c3.x;
    const int s11 = s12 + (int)c2.w;
    const int s10 = s11 + (int)c2.z;
    const int s9  = s10 + (int)c2.y;
    const int s8  = s9  + (int)c2.x;
    const int s7  = s8  + (int)c1.w;
    const int s6  = s7  + (int)c1.z;
    const int s5  = s6  + (int)c1.y;
    const int s4  = s5  + (int)c1.x;
    const int s3  = s4  + (int)c0.w;
    const int s2  = s3  + (int)c0.z;
    const int s1  = s2  + (int)c0.y;
    const int s0  = s1  + (int)c0.x;
    const unsigned p0 = (unsigned)s0  | ((unsigned)s1  << 8) |
                        ((unsigned)s2  << 16) | ((unsigned)s3  << 24);
    const unsigned p1 = (unsigned)s4  | ((unsigned)s5  << 8) |
                        ((unsigned)s6  << 16) | ((unsigned)s7  << 24);
    const unsigned p2 = (unsigned)s8  | ((unsigned)s9  << 8) |
                        ((unsigned)s10 << 16) | ((unsigned)s11 << 24);
    const unsigned p3 = (unsigned)s12 | ((unsigned)s13 << 8) |
                        ((unsigned)s14 << 16) | ((unsigned)s15 << 24);

    // Inclusive suffix sum of chunk totals over lanes sub..15 in the group.
    int suf = s0;
    #pragma unroll
    for (int d = 1; d < 16; d <<= 1) {
        int t = __shfl_down_sync(FULLMASK, suf, d);
        if (sub + d < 16) suf += t;
    }

    const float t1 = sel_kth< 96>(s0, p0, p1, p2, p3, suf, v, bin, gmask, gsh);
    const float t2 = sel_kth<128>(s0, p0, p1, p2, p3, suf, v, bin, gmask, gsh);
    const float t3 = sel_kth<144>(s0, p0, p1, p2, p3, suf, v, bin, gmask, gsh);
    const float t4 = sel_kth<153>(s0, p0, p1, p2, p3, suf, v, bin, gmask, gsh);

    // Float masked partition sums (fma pipe), one fixed-point convert per
    // accumulator, group REDUX.SUM. Shift by t1 bounds every term (~e^6),
    // so sums fit u32 at scale 2^14 with large slack.
    float z1 = 0.f, z2 = 0.f, z3 = 0.f, z4 = 0.f;
    #pragma unroll
    for (int j = 0; j < VPT; j++) {
        const float e = __expf(v[j] - t1);
        z1 += (v[j] >= t1) ? e : 0.f;
        z2 += (v[j] >= t2) ? e : 0.f;
        z3 += (v[j] >= t3) ? e : 0.f;
        z4 += (v[j] >= t4) ? e : 0.f;
    }
    const unsigned zu1 = __reduce_add_sync(gmask, (unsigned)(z1 * FPSCALE));
    const unsigned zu2 = __reduce_add_sync(gmask, (unsigned)(z2 * FPSCALE));
    const unsigned zu3 = __reduce_add_sync(gmask, (unsigned)(z3 * FPSCALE));
    const unsigned zu4 = __reduce_add_sync(gmask, (unsigned)(z4 * FPSCALE));

    const float q1 = __fdividef(*w1p, (float)zu1 * IFPSCALE);
    const float q2 = __fdividef(*w2p, (float)zu2 * IFPSCALE);
    const float q3 = __fdividef(*w3p, (float)zu3 * IFPSCALE);
    const float q4 = __fdividef(*w4p, (float)zu4 * IFPSCALE);
    // Cumulative: passing t_i implies passing all lower thresholds.
    const float C4 = q4;
    const float C3 = C4 + q3;
    const float C2 = C3 + q2;
    const float C1 = C2 + q1;

    float2* op2 = reinterpret_cast<float2*>(out + row * (long long)C);
    #pragma unroll
    for (int jj = 0; jj < 6; jj++) {
        float2 o;
        #pragma unroll
        for (int h = 0; h < 2; h++) {
            const float vv = v[2 * jj + h];
            float c = 0.f;
            c = (vv >= t4) ? C4 : c;
            c = (vv >= t3) ? C3 : c;
            c = (vv >= t2) ? C2 : c;
            c = (vv >= t1) ? C1 : c;
            const float r = __expf(vv - t1) * c;
            if (h == 0) o.x = r; else o.y = r;
        }
        op2[sub + 16 * jj] = o;
    }
}

extern "C" void kernel_launch(void* const* d_in, const int* in_sizes, int n_in,
                              void* d_out, int out_size)
{
    const float* attn = (const float*)d_in[0];
    const float* w1   = (const float*)d_in[1];
    const float* w2   = (const float*)d_in[2];
    const float* w3   = (const float*)d_in[3];
    const float* w4   = (const float*)d_in[4];
    float* out = (float*)d_out;

    const int nrows = in_sizes[0] / C;  // 98304
    const int blocks = (nrows + RPB - 1) / RPB;
    sparsify_attention_kernel<<<blocks, 256>>>(
        attn, w1, w2, w3, w4, out, nrows);
}

// round 15
// speedup vs baseline: 1.4199x; 1.4199x over previous
#include <cuda_runtime.h>

// SparsifyAttention: attn [64,8,192,192] fp32.
// out[j] = exp(v_j - t1) * sum_i [v_j >= t_i] * w_i / Z_i,
//   Z_i = sum_{v>=t_i} exp(v - t1)   (shift-invariant softmax).
// t_i = {96,128,144,153}-th largest per row.
//
// One warp per row, 6 vals/lane. 256-bin histogram over [-1.6, 0.8].
// Selection trick: keep the pre-truncation bin key f = sat((v-BLO)/W)*255
// in registers; "bin(v) <= b" is exactly "f < (float)(b+1)" — the compare
// is bit-consistent with the histogram binning, so the bin-interval max
// (max{v : bin(v) <= b} = max of bin b, which is nonempty) needs no
// integer membership tests. Exact for any input; rare ties walked exactly.

#define FULLMASK 0xffffffffu

constexpr int   C     = 192;
constexpr int   VPT   = 6;
constexpr int   WARPS = 8;
constexpr int   NBINS = 256;
constexpr float BLO   = -1.6f;
constexpr float BHI   = 0.8f;
constexpr float BINV  = 1.0f / (BHI - BLO);
constexpr float FPSCALE  = 16384.0f;        // 2^14
constexpr float IFPSCALE = 1.0f / 16384.0f;

__device__ __forceinline__ unsigned f2ord(float f) {
    unsigned u = __float_as_uint(f);
    unsigned m = (unsigned)(((int)u) >> 31) | 0x80000000u;
    return u ^ m;
}
__device__ __forceinline__ float ord2f(unsigned x) {
    unsigned m = (~(unsigned)(((int)x) >> 31)) | 0x80000000u;
    return __uint_as_float(x ^ m);
}

// K-th largest (1-based, multiset) of the warp's 192 values.
// S0: lane's 8-bin chunk total; p0/p1: byte-packed suffix sums S[0..7]
// (S[i] = count in bins [8L+i, 8L+8), <= 192); suf: inclusive suffix of
// S0 over lanes >= lane. fb[j]: pre-truncation bin keys (floor(fb) = bin).
template <int K>
__device__ __forceinline__ float sel_kth(
    int S0, unsigned p0, unsigned p1, int suf,
    const float v[VPT], const float fb[VPT])
{
    const int above = suf - S0;
    const int r0 = K - above;              // meaningful on owning lane only
    const int r0c = max(1, min(255, r0));
    const unsigned sp = (unsigned)r0c * 0x01010101u;
    // i = (# of S[j] >= r0) - 1 : threshold bin index within the chunk.
    const int cnt = __popc(__vcmpgeu4(p0, sp)) + __popc(__vcmpgeu4(p1, sp));
    const int i = (cnt >> 3) - 1;
    // S[i+1] (S[8] = 0): count in bins above bin i within the chunk.
    const int sip1 = (i >= 7) ? 0 : (int)(__byte_perm(p0, p1, i + 1) & 0xFFu);
    const int r_loc = r0 - sip1;           // rank within bin, from top

    const unsigned ball = __ballot_sync(FULLMASK, (suf >= K) && (above < K));
    const int L = __ffs(ball) - 1;
    const int b = 8 * L + __shfl_sync(FULLMASK, i, L);
    const int r = __shfl_sync(FULLMASK, r_loc, L);

    const float INF = __int_as_float(0x7f800000);
    // bin(v) <= b  <=>  fb < (float)(b+1): exact, same function as binning.
    const float bF = (float)(b + 1);

    // Max over {bin <= b} == max of bin b (bin b is nonempty: holds rank K).
    float loc = -INF;
    #pragma unroll
    for (int j = 0; j < VPT; j++)
        loc = (fb[j] < bF) ? fmaxf(loc, v[j]) : loc;
    float cur = ord2f(__reduce_max_sync(FULLMASK, f2ord(loc)));

    if (r > 1) {  // warp-uniform, rare: walk down distinct values in bin b
        int eq = 0;
        #pragma unroll
        for (int j = 0; j < VPT; j++) eq += (v[j] == cur);
        int need = r - (int)__reduce_add_sync(FULLMASK, (unsigned)eq);
        while (need > 0) {
            const float bound = cur;       // stays within bin b while need>0
            loc = -INF;
            #pragma unroll
            for (int j = 0; j < VPT; j++)
                loc = (fb[j] < bF && v[j] < bound) ? fmaxf(loc, v[j]) : loc;
            cur = ord2f(__reduce_max_sync(FULLMASK, f2ord(loc)));
            eq = 0;
            #pragma unroll
            for (int j = 0; j < VPT; j++) eq += (v[j] == cur);
            need -= (int)__reduce_add_sync(FULLMASK, (unsigned)eq);
        }
    }
    return cur;
}

__global__ __launch_bounds__(32 * WARPS, 6)
void sparsify_attention_kernel(
    const float* __restrict__ attn,
    const float* __restrict__ w1p, const float* __restrict__ w2p,
    const float* __restrict__ w3p, const float* __restrict__ w4p,
    float* __restrict__ out, int nrows)
{
    __shared__ unsigned hist_s[WARPS][NBINS];

    const int lane = threadIdx.x & 31;
    const int wid  = threadIdx.x >> 5;
    const long long row = (long long)blockIdx.x * WARPS + wid;
    if (row >= nrows) return;

    unsigned* hist = hist_s[wid];

    // Zero histogram (two 128-bit stores per lane).
    const uint4 zz = make_uint4(0, 0, 0, 0);
    *reinterpret_cast<uint4*>(&hist[lane * 8])     = zz;
    *reinterpret_cast<uint4*>(&hist[lane * 8 + 4]) = zz;
    __syncwarp();

    // Vectorized row load.
    const float2* rp2 = reinterpret_cast<const float2*>(attn + row * (long long)C);
    float v[VPT];
    #pragma unroll
    for (int jj = 0; jj < 3; jj++) {
        float2 f = rp2[lane + 32 * jj];
        v[2 * jj]     = f.x;
        v[2 * jj + 1] = f.y;
    }

    // Bin keys (kept in registers; floor(fb) = bin index) + histogram.
    float fb[VPT];
    #pragma unroll
    for (int j = 0; j < VPT; j++) {
        fb[j] = __saturatef((v[j] - BLO) * BINV) * 255.0f;
        atomicAdd(&hist[(int)fb[j]], 1u);
    }
    __syncwarp();

    // Chunk counts -> suffix sums, packed into bytes (all <= 192 < 256).
    const uint4 ca = *reinterpret_cast<const uint4*>(&hist[lane * 8]);
    const uint4 cb = *reinterpret_cast<const uint4*>(&hist[lane * 8 + 4]);
    const int S7 = (int)cb.w;
    const int S6 = S7 + (int)cb.z;
    const int S5 = S6 + (int)cb.y;
    const int S4 = S5 + (int)cb.x;
    const int S3 = S4 + (int)ca.w;
    const int S2 = S3 + (int)ca.z;
    const int S1 = S2 + (int)ca.y;
    const int S0 = S1 + (int)ca.x;
    const unsigned p0 = (unsigned)S0 | ((unsigned)S1 << 8) |
                        ((unsigned)S2 << 16) | ((unsigned)S3 << 24);
    const unsigned p1 = (unsigned)S4 | ((unsigned)S5 << 8) |
                        ((unsigned)S6 << 16) | ((unsigned)S7 << 24);

    // Inclusive suffix sum of chunk totals over lanes >= lane.
    int suf = S0;
    #pragma unroll
    for (int d = 1; d < 32; d <<= 1) {
        int t = __shfl_down_sync(FULLMASK, suf, d);
        if (lane + d < 32) suf += t;
    }

    const float t1 = sel_kth< 96>(S0, p0, p1, suf, v, fb);
    const float t2 = sel_kth<128>(S0, p0, p1, suf, v, fb);
    const float t3 = sel_kth<144>(S0, p0, p1, suf, v, fb);
    const float t4 = sel_kth<153>(S0, p0, p1, suf, v, fb);

    // Float masked partition sums (fma pipe), one fixed-point convert per
    // accumulator, REDUX.SUM. Shift by t1 bounds every term (~e^6.5), so
    // sums fit u32 at scale 2^14 with large slack; quant err <= 2e-5 rel.
    float e[VPT];
    float z1 = 0.f, z2 = 0.f, z3 = 0.f, z4 = 0.f;
    #pragma unroll
    for (int j = 0; j < VPT; j++) {
        e[j] = __expf(v[j] - t1);
        z1 += (v[j] >= t1) ? e[j] : 0.f;
        z2 += (v[j] >= t2) ? e[j] : 0.f;
        z3 += (v[j] >= t3) ? e[j] : 0.f;
        z4 += (v[j] >= t4) ? e[j] : 0.f;
    }
    const unsigned zu1 = __reduce_add_sync(FULLMASK, (unsigned)(z1 * FPSCALE));
    const unsigned zu2 = __reduce_add_sync(FULLMASK, (unsigned)(z2 * FPSCALE));
    const unsigned zu3 = __reduce_add_sync(FULLMASK, (unsigned)(z3 * FPSCALE));
    const unsigned zu4 = __reduce_add_sync(FULLMASK, (unsigned)(z4 * FPSCALE));

    const float q1 = __fdividef(*w1p, (float)zu1 * IFPSCALE);
    const float q2 = __fdividef(*w2p, (float)zu2 * IFPSCALE);
    const float q3 = __fdividef(*w3p, (float)zu3 * IFPSCALE);
    const float q4 = __fdividef(*w4p, (float)zu4 * IFPSCALE);
    // Cumulative: passing t_i implies passing all lower thresholds.
    const float C4 = q4;
    const float C3 = C4 + q3;
    const float C2 = C3 + q2;
    const float C1 = C2 + q1;

    float2* op2 = reinterpret_cast<float2*>(out + row * (long long)C);
    #pragma unroll
    for (int jj = 0; jj < 3; jj++) {
        float2 o;
        #pragma unroll
        for (int h = 0; h < 2; h++) {
            const float vv = v[2 * jj + h];
            float c = 0.f;
            c = (vv >= t4) ? C4 : c;
            c = (vv >= t3) ? C3 : c;
            c = (vv >= t2) ? C2 : c;
            c = (vv >= t1) ? C1 : c;
            const float r = e[2 * jj + h] * c;
            if (h == 0) o.x = r; else o.y = r;
        }
        op2[lane + 32 * jj] = o;
    }
}

extern "C" void kernel_launch(void* const* d_in, const int* in_sizes, int n_in,
                              void* d_out, int out_size)
{
    const float* attn = (const float*)d_in[0];
    const float* w1   = (const float*)d_in[1];
    const float* w2   = (const float*)d_in[2];
    const float* w3   = (const float*)d_in[3];
    const float* w4   = (const float*)d_in[4];
    float* out = (float*)d_out;

    const int nrows = in_sizes[0] / C;  // 98304
    const int blocks = (nrows + WARPS - 1) / WARPS;
    sparsify_attention_kernel<<<blocks, 32 * WARPS>>>(
        attn, w1, w2, w3, w4, out, nrows);
}

// round 17
// speedup vs baseline: 1.4640x; 1.0310x over previous
#include <cuda_runtime.h>

// SparsifyAttention: attn [64,8,192,192] fp32.
// out[j] = exp(v_j - t1) * sum_i [v_j >= t_i] * w_i / Z_i,
//   Z_i = sum_{v>=t_i} exp(v - t1)   (shift-invariant softmax).
// t_i = {96,128,144,153}-th largest per row.
//
// One warp per row, 6 vals/lane. 256-bin histogram over [-1.6, 0.8].
// Select: pre-truncation bin key fb kept in registers; "bin(v) <= b" is
// exactly "fb < (float)(b+1)" (bit-consistent with binning), so in-bin
// max needs no integer membership tests. Exact for any input.
// NEW: all masked accumulations (z partition sums, epilogue weight sums)
// use inline-PTX predicated FADD (setp + @p add) — fma pipe, no SEL/FSEL
// on the saturated alu pipe, no branches.

#define FULLMASK 0xffffffffu

// Predicated accumulate: if (a >= b) acc += addend;  (FSETP + @P FADD)
#define PACC_GE(acc, a, b, addend)                                  \
    asm("{ .reg .pred p; setp.ge.f32 p, %1, %2;"                    \
        "  @p add.f32 %0, %0, %3; }"                                \
        : "+f"(acc) : "f"(a), "f"(b), "f"(addend))

constexpr int   C     = 192;
constexpr int   VPT   = 6;
constexpr int   WARPS = 8;
constexpr int   NBINS = 256;
constexpr float BLO   = -1.6f;
constexpr float BHI   = 0.8f;
constexpr float BINV  = 1.0f / (BHI - BLO);
constexpr float FPSCALE  = 16384.0f;        // 2^14
constexpr float IFPSCALE = 1.0f / 16384.0f;

__device__ __forceinline__ unsigned f2ord(float f) {
    unsigned u = __float_as_uint(f);
    unsigned m = (unsigned)(((int)u) >> 31) | 0x80000000u;
    return u ^ m;
}
__device__ __forceinline__ float ord2f(unsigned x) {
    unsigned m = (~(unsigned)(((int)x) >> 31)) | 0x80000000u;
    return __uint_as_float(x ^ m);
}

// K-th largest (1-based, multiset) of the warp's 192 values.
template <int K>
__device__ __forceinline__ float sel_kth(
    int S0, unsigned p0, unsigned p1, int suf,
    const float v[VPT], const float fb[VPT])
{
    const int above = suf - S0;
    const int r0 = K - above;              // meaningful on owning lane only
    const int r0c = max(1, min(255, r0));
    const unsigned sp = (unsigned)r0c * 0x01010101u;
    const int cnt = __popc(__vcmpgeu4(p0, sp)) + __popc(__vcmpgeu4(p1, sp));
    const int i = (cnt >> 3) - 1;
    const int sip1 = (i >= 7) ? 0 : (int)(__byte_perm(p0, p1, i + 1) & 0xFFu);
    const int r_loc = r0 - sip1;           // rank within bin, from top

    const unsigned ball = __ballot_sync(FULLMASK, (suf >= K) && (above < K));
    const int L = __ffs(ball) - 1;
    const int b = 8 * L + __shfl_sync(FULLMASK, i, L);
    const int r = __shfl_sync(FULLMASK, r_loc, L);

    const float INF = __int_as_float(0x7f800000);
    const float bF = (float)(b + 1);       // bin(v) <= b  <=>  fb < bF (exact)

    float loc = -INF;
    #pragma unroll
    for (int j = 0; j < VPT; j++)
        loc = (fb[j] < bF) ? fmaxf(loc, v[j]) : loc;
    float cur = ord2f(__reduce_max_sync(FULLMASK, f2ord(loc)));

    if (r > 1) {  // warp-uniform, rare: walk down distinct values in bin b
        int eq = 0;
        #pragma unroll
        for (int j = 0; j < VPT; j++) eq += (v[j] == cur);
        int need = r - (int)__reduce_add_sync(FULLMASK, (unsigned)eq);
        while (need > 0) {
            const float bound = cur;
            loc = -INF;
            #pragma unroll
            for (int j = 0; j < VPT; j++)
                loc = (fb[j] < bF && v[j] < bound) ? fmaxf(loc, v[j]) : loc;
            cur = ord2f(__reduce_max_sync(FULLMASK, f2ord(loc)));
            eq = 0;
            #pragma unroll
            for (int j = 0; j < VPT; j++) eq += (v[j] == cur);
            need -= (int)__reduce_add_sync(FULLMASK, (unsigned)eq);
        }
    }
    return cur;
}

__global__ __launch_bounds__(32 * WARPS, 6)
void sparsify_attention_kernel(
    const float* __restrict__ attn,
    const float* __restrict__ w1p, const float* __restrict__ w2p,
    const float* __restrict__ w3p, const float* __restrict__ w4p,
    float* __restrict__ out, int nrows)
{
    __shared__ unsigned hist_s[WARPS][NBINS];

    const int lane = threadIdx.x & 31;
    const int wid  = threadIdx.x >> 5;
    const long long row = (long long)blockIdx.x * WARPS + wid;
    if (row >= nrows) return;

    unsigned* hist = hist_s[wid];

    // Zero histogram (two 128-bit stores per lane).
    const uint4 zz = make_uint4(0, 0, 0, 0);
    *reinterpret_cast<uint4*>(&hist[lane * 8])     = zz;
    *reinterpret_cast<uint4*>(&hist[lane * 8 + 4]) = zz;
    __syncwarp();

    // Vectorized row load.
    const float2* rp2 = reinterpret_cast<const float2*>(attn + row * (long long)C);
    float v[VPT];
    #pragma unroll
    for (int jj = 0; jj < 3; jj++) {
        float2 f = rp2[lane + 32 * jj];
        v[2 * jj]     = f.x;
        v[2 * jj + 1] = f.y;
    }

    // Bin keys (floor(fb) = bin index) + histogram.
    float fb[VPT];
    #pragma unroll
    for (int j = 0; j < VPT; j++) {
        fb[j] = __saturatef((v[j] - BLO) * BINV) * 255.0f;
        atomicAdd(&hist[(int)fb[j]], 1u);
    }
    __syncwarp();

    // Chunk counts -> suffix sums, packed into bytes (all <= 192 < 256).
    const uint4 ca = *reinterpret_cast<const uint4*>(&hist[lane * 8]);
    const uint4 cb = *reinterpret_cast<const uint4*>(&hist[lane * 8 + 4]);
    const int S7 = (int)cb.w;
    const int S6 = S7 + (int)cb.z;
    const int S5 = S6 + (int)cb.y;
    const int S4 = S5 + (int)cb.x;
    const int S3 = S4 + (int)ca.w;
    const int S2 = S3 + (int)ca.z;
    const int S1 = S2 + (int)ca.y;
    const int S0 = S1 + (int)ca.x;
    const unsigned p0 = (unsigned)S0 | ((unsigned)S1 << 8) |
                        ((unsigned)S2 << 16) | ((unsigned)S3 << 24);
    const unsigned p1 = (unsigned)S4 | ((unsigned)S5 << 8) |
                        ((unsigned)S6 << 16) | ((unsigned)S7 << 24);

    // Inclusive suffix sum of chunk totals over lanes >= lane.
    int suf = S0;
    #pragma unroll
    for (int d = 1; d < 32; d <<= 1) {
        int t = __shfl_down_sync(FULLMASK, suf, d);
        if (lane + d < 32) suf += t;
    }

    const float t1 = sel_kth< 96>(S0, p0, p1, suf, v, fb);
    const float t2 = sel_kth<128>(S0, p0, p1, suf, v, fb);
    const float t3 = sel_kth<144>(S0, p0, p1, suf, v, fb);
    const float t4 = sel_kth<153>(S0, p0, p1, suf, v, fb);

    // Masked partition sums: predicated FADDs (fma pipe, no SEL), then one
    // fixed-point convert per accumulator + REDUX.SUM. Shift by t1 bounds
    // every term (~e^6.5), sums fit u32 at 2^14; quant err <= 2e-5 rel.
    float e[VPT];
    float z1 = 0.f, z2 = 0.f, z3 = 0.f, z4 = 0.f;
    #pragma unroll
    for (int j = 0; j < VPT; j++) {
        e[j] = __expf(v[j] - t1);
        PACC_GE(z1, v[j], t1, e[j]);
        PACC_GE(z2, v[j], t2, e[j]);
        PACC_GE(z3, v[j], t3, e[j]);
        PACC_GE(z4, v[j], t4, e[j]);
    }
    const unsigned zu1 = __reduce_add_sync(FULLMASK, (unsigned)(z1 * FPSCALE));
    const unsigned zu2 = __reduce_add_sync(FULLMASK, (unsigned)(z2 * FPSCALE));
    const unsigned zu3 = __reduce_add_sync(FULLMASK, (unsigned)(z3 * FPSCALE));
    const unsigned zu4 = __reduce_add_sync(FULLMASK, (unsigned)(z4 * FPSCALE));

    const float q1 = __fdividef(*w1p, (float)zu1 * IFPSCALE);
    const float q2 = __fdividef(*w2p, (float)zu2 * IFPSCALE);
    const float q3 = __fdividef(*w3p, (float)zu3 * IFPSCALE);
    const float q4 = __fdividef(*w4p, (float)zu4 * IFPSCALE);

    // Epilogue: additive weight sum via predicated FADDs (no SEL cascade).
    float2* op2 = reinterpret_cast<float2*>(out + row * (long long)C);
    #pragma unroll
    for (int jj = 0; jj < 3; jj++) {
        float2 o;
        #pragma unroll
        for (int h = 0; h < 2; h++) {
            const float vv = v[2 * jj + h];
            float c = 0.f;
            PACC_GE(c, vv, t1, q1);
            PACC_GE(c, vv, t2, q2);
            PACC_GE(c, vv, t3, q3);
            PACC_GE(c, vv, t4, q4);
            const float r = e[2 * jj + h] * c;
            if (h == 0) o.x = r; else o.y = r;
        }
        op2[lane + 32 * jj] = o;
    }
}

extern "C" void kernel_launch(void* const* d_in, const int* in_sizes, int n_in,
                              void* d_out, int out_size)
{
    const float* attn = (const float*)d_in[0];
    const float* w1   = (const float*)d_in[1];
    const float* w2   = (const float*)d_in[2];
    const float* w3   = (const float*)d_in[3];
    const float* w4   = (const float*)d_in[4];
    float* out = (float*)d_out;

    const int nrows = in_sizes[0] / C;  // 98304
    const int blocks = (nrows + WARPS - 1) / WARPS;
    sparsify_attention_kernel<<<blocks, 32 * WARPS>>>(
        attn, w1, w2, w3, w4, out, nrows);
}